// round 17
// baseline (speedup 1.0000x reference)
#include <cuda_runtime.h>
#include <cuda_fp16.h>
#include <mma.h>
#include <cstdint>

using namespace nvcuda;

// Problem constants
constexpr int Bc  = 2;
constexpr int Lc  = 2048;
constexpr int Dc  = 2048;
constexpr int Hc  = 16;
constexpr int DHc = 128;

constexpr int BDIM = 256;
__device__ __constant__ float SCALE_C = 0.08838834764831845f; // 1/sqrt(128)

// Scratch (static device globals: allocation-free per harness rules), fp16
__device__ __half g_Qh[(size_t)Bc * Hc * Lc * DHc];
__device__ __half g_Kh[(size_t)Bc * Hc * Lc * DHc];
__device__ __half g_Vh[(size_t)Bc * Hc * Lc * DHc];
__device__ __half g_Ah[(size_t)Bc * Lc * Dc];
__device__ __half g_Xh[(size_t)Bc * Lc * Dc];
__device__ __half g_Wqh[(size_t)Dc * Dc];
__device__ __half g_Wkh[(size_t)Dc * Dc];
__device__ __half g_Wvh[(size_t)Dc * Dc];
__device__ __half g_Woh[(size_t)Dc * Dc];

// ---------------------------------------------------------------------------
// cp.async helpers
// ---------------------------------------------------------------------------
__device__ __forceinline__ void cp_async16(void* smem_dst, const void* gmem_src) {
    unsigned s = (unsigned)__cvta_generic_to_shared(smem_dst);
    asm volatile("cp.async.cg.shared.global [%0], [%1], 16;\n" :: "r"(s), "l"(gmem_src));
}
__device__ __forceinline__ void cp_commit() {
    asm volatile("cp.async.commit_group;\n");
}
template <int N>
__device__ __forceinline__ void cp_wait() {
    asm volatile("cp.async.wait_group %0;\n" :: "n"(N));
}

// ---------------------------------------------------------------------------
// Convert inputs to fp16. 8 elements per thread.
// ---------------------------------------------------------------------------
__global__ void __launch_bounds__(256)
cvt_kernel(const float* __restrict__ x,  const float* __restrict__ wq,
           const float* __restrict__ wk, const float* __restrict__ wv,
           const float* __restrict__ wo) {
    constexpr size_t NX = (size_t)Bc * Lc * Dc;   // 8388608
    constexpr size_t NW = (size_t)Dc * Dc;        // 4194304
    size_t i = ((size_t)blockIdx.x * 256 + threadIdx.x) * 8;
    const float* src; __half* dst;
    if (i < NX)                { src = x  + i;               dst = g_Xh  + i; }
    else if (i < NX + NW)      { src = wq + (i - NX);        dst = g_Wqh + (i - NX); }
    else if (i < NX + 2 * NW)  { src = wk + (i - NX - NW);   dst = g_Wkh + (i - NX - NW); }
    else if (i < NX + 3 * NW)  { src = wv + (i - NX - 2*NW); dst = g_Wvh + (i - NX - 2*NW); }
    else if (i < NX + 4 * NW)  { src = wo + (i - NX - 3*NW); dst = g_Woh + (i - NX - 3*NW); }
    else return;
    float4 a = ((const float4*)src)[0];
    float4 b = ((const float4*)src)[1];
    __half2 h0 = __floats2half2_rn(a.x, a.y);
    __half2 h1 = __floats2half2_rn(a.z, a.w);
    __half2 h2 = __floats2half2_rn(b.x, b.y);
    __half2 h3 = __floats2half2_rn(b.z, b.w);
    uint4 packed;
    packed.x = *(uint32_t*)&h0; packed.y = *(uint32_t*)&h1;
    packed.z = *(uint32_t*)&h2; packed.w = *(uint32_t*)&h3;
    *(uint4*)dst = packed;
}

// ---------------------------------------------------------------------------
// fp16 WMMA GEMM core, 3-stage cp.async pipeline, K-chunk = 64 (1 barrier per
// chunk, 32 chunks). 128x128 tile of C = X * W^T (K = Dc), fp32 accumulate.
// smem: 6 half buffers [128][72] (18432 B each -> 110592 B); result tile
// cs[128][132] fp32 (67584 B) reuses the region when DIRECT=false.
// ---------------------------------------------------------------------------
constexpr int HST   = 72;                 // half stride (mult of 8)
constexpr int HBUFB = 128 * HST * 2;      // 18432 bytes per stage buffer
constexpr int NSTG  = 3;
constexpr int NC_H  = Dc / 64;            // 32 chunks of K=64

__device__ __forceinline__ void ld_chunk_h(const __half* __restrict__ X,
                                           const __half* __restrict__ W,
                                           char* xs, char* ws,
                                           int m0, int n0, int k0, int tid) {
#pragma unroll
    for (int i = 0; i < 4; i++) {
        int fi = tid + BDIM * i;          // 1024 float4 per matrix
        int r  = fi >> 3;                 // 8 f4 per 64-half row
        int c8 = (fi & 7) * 8;
        cp_async16(xs + (r * HST + c8) * 2, X + (size_t)(m0 + r) * Dc + k0 + c8);
        cp_async16(ws + (r * HST + c8) * 2, W + (size_t)(n0 + r) * Dc + k0 + c8);
    }
}

template <bool DIRECT>
__device__ __forceinline__ void gemm_core_h(const __half* __restrict__ X,
                                            const __half* __restrict__ W,
                                            char* smc, float* gout) {
    const int tid = threadIdx.x;
    const int m0 = blockIdx.y * 128;
    const int n0 = blockIdx.x * 128;
    char* xb = smc;                       // 3 x [128][72] half
    char* wb = smc + NSTG * HBUFB;
    const int warp = tid >> 5;
    const int wm = warp & 3;              // 4 warps along M (32 rows)
    const int wn = warp >> 2;             // 2 warps along N (64 cols)

    wmma::fragment<wmma::accumulator, 16, 16, 16, float> cf[2][4];
#pragma unroll
    for (int i = 0; i < 2; i++)
#pragma unroll
        for (int j = 0; j < 4; j++)
            wmma::fill_fragment(cf[i][j], 0.0f);

    ld_chunk_h(X, W, xb, wb, m0, n0, 0, tid);
    cp_commit();
    ld_chunk_h(X, W, xb + HBUFB, wb + HBUFB, m0, n0, 64, tid);
    cp_commit();

    int buf = 0;
    for (int c = 0; c < NC_H; c++) {
        cp_wait<1>();                     // chunk c landed
        __syncthreads();                  // visible; buffer (c+2)%3 free
        if (c + 2 < NC_H) {
            int nb = buf + 2; if (nb >= NSTG) nb -= NSTG;
            ld_chunk_h(X, W, xb + nb * HBUFB, wb + nb * HBUFB,
                       m0, n0, (c + 2) * 64, tid);
        }
        cp_commit();                      // keep group count exact

        const __half* xs = (const __half*)(xb + buf * HBUFB);
        const __half* ws = (const __half*)(wb + buf * HBUFB);
#pragma unroll
        for (int kk = 0; kk < 64; kk += 16) {
            wmma::fragment<wmma::matrix_a, 16, 16, 16, __half, wmma::row_major> af[2];
            wmma::fragment<wmma::matrix_b, 16, 16, 16, __half, wmma::col_major> bf[4];
#pragma unroll
            for (int i = 0; i < 2; i++)
                wmma::load_matrix_sync(af[i], xs + (wm * 32 + i * 16) * HST + kk, HST);
#pragma unroll
            for (int j = 0; j < 4; j++)
                wmma::load_matrix_sync(bf[j], ws + (wn * 64 + j * 16) * HST + kk, HST);
#pragma unroll
            for (int i = 0; i < 2; i++)
#pragma unroll
                for (int j = 0; j < 4; j++)
                    wmma::mma_sync(cf[i][j], af[i], bf[j], cf[i][j]);
        }
        buf++; if (buf == NSTG) buf = 0;
    }

    if (DIRECT) {
        // Store fragments straight to gmem (row-major, ldm = Dc)
#pragma unroll
        for (int i = 0; i < 2; i++)
#pragma unroll
            for (int j = 0; j < 4; j++)
                wmma::store_matrix_sync(gout + (size_t)(m0 + wm * 32 + i * 16) * Dc
                                             + n0 + wn * 64 + j * 16,
                                        cf[i][j], Dc, wmma::mem_row_major);
    } else {
        __syncthreads();
        float* cs = (float*)smc;          // [128][132]
#pragma unroll
        for (int i = 0; i < 2; i++)
#pragma unroll
            for (int j = 0; j < 4; j++)
                wmma::store_matrix_sync(cs + (wm * 32 + i * 16) * 132 + wn * 64 + j * 16,
                                        cf[i][j], 132, wmma::mem_row_major);
        __syncthreads();
    }
}

// ---------------------------------------------------------------------------
// QKV projection + fused RoPE. grid = (16, 32, 3); outputs fp16 [B,H,L,DH].
// ---------------------------------------------------------------------------
__global__ void __launch_bounds__(BDIM, 2)
proj_kernel(const float* __restrict__ cosT, const float* __restrict__ sinT) {
    extern __shared__ __align__(16) char smc[];
    const int z = blockIdx.z;
    const __half* W = (z == 0) ? g_Wqh : (z == 1) ? g_Wkh : g_Wvh;
    __half* O = (z == 0) ? g_Qh : (z == 1) ? g_Kh : g_Vh;

    gemm_core_h<false>(g_Xh, W, smc, nullptr);

    float* cs = (float*)smc;
    const int m0 = blockIdx.y * 128;
    const int n0 = blockIdx.x * 128;
    const int h  = n0 / DHc;              // each 128-wide N tile is one head
    const int tid = threadIdx.x;

    if (z < 2) {
        for (int idx = tid; idx < 128 * 64; idx += BDIM) {
            int r = idx >> 6, p = idx & 63;
            int m = m0 + r;
            int l = m & (Lc - 1);
            int bi = m >> 11;
            float t1 = cs[r * 132 + 2 * p];
            float t2 = cs[r * 132 + 2 * p + 1];
            float c = cosT[l * 64 + p];
            float s = sinT[l * 64 + p];
            size_t base = (((size_t)(bi * Hc + h) * Lc + l) * DHc) + 2 * p;
            O[base]     = __float2half(t1 * c - t2 * s);
            O[base + 1] = __float2half(t1 * s + t2 * c);
        }
    } else {
        for (int idx = tid; idx < 128 * 128; idx += BDIM) {
            int r = idx >> 7, d = idx & 127;
            int m = m0 + r;
            int l = m & (Lc - 1);
            int bi = m >> 11;
            O[(((size_t)(bi * Hc + h) * Lc + l) * DHc) + d] = __float2half(cs[r * 132 + d]);
        }
    }
}

// ---------------------------------------------------------------------------
// Flash attention (causal), fp16 operands / fp32 softmax+accum.
// 128-query tile per CTA, grid = (L/128, H, B), reversed tile order.
// Warp w owns Q-row band [w*16, w*16+16); 8 persistent accum fragments/warp.
// smem (bytes):
//   Qs half[128][136] @0       34816
//   KB 2x half[64][136] @34816 34816
//   VB 2x half[64][136] @69632 34816
//   Ss float[128][68] @104448  34816
//   Ps half[128][72]  @139264  18432
//   Ar float[128]     @157696,  Lr float[128] @158208 -> 158720 total
//   Ac float[128][132] reuses @0 (Qs+KB region, dead at epilogue)
// ---------------------------------------------------------------------------
constexpr int QST = 136;            // half stride for Q/K/V rows
constexpr int PST = 72;             // half stride for P
constexpr int KVB = 64 * QST * 2;   // 17408 bytes per K/V stage

__device__ __forceinline__ void ld_kv_h(const __half* __restrict__ Kp,
                                        const __half* __restrict__ Vp,
                                        char* Ks, char* Vs, int k0, int tid) {
#pragma unroll
    for (int i = 0; i < 4; i++) {
        int fi = tid + BDIM * i;          // 1024 float4 per matrix
        int r  = fi >> 4;                 // 16 f4 per 128-half row
        int c8 = (fi & 15) * 8;
        cp_async16(Ks + (r * QST + c8) * 2, Kp + (size_t)(k0 + r) * DHc + c8);
        cp_async16(Vs + (r * QST + c8) * 2, Vp + (size_t)(k0 + r) * DHc + c8);
    }
}

__global__ void __launch_bounds__(BDIM) attn_kernel() {
    extern __shared__ __align__(16) char smc[];
    __half* Qs = (__half*)smc;
    char*   KB = smc + 34816;
    char*   VB = smc + 69632;
    float*  Ss = (float*)(smc + 104448);
    __half* Ps = (__half*)(smc + 139264);
    float*  Ar = (float*)(smc + 157696);
    float*  Lr = (float*)(smc + 158208);
    float*  Ac = (float*)smc;            // epilogue only (reuses Qs+KB)

    const int tid  = threadIdx.x;
    const int warp = tid >> 5;
    const int q0 = (int)(gridDim.x - 1 - blockIdx.x) * 128;
    const int h  = blockIdx.y;
    const int bb = blockIdx.z;
    const size_t head_off = ((size_t)(bb * Hc + h) * Lc) * DHc;
    const __half* Qp = g_Qh + head_off;
    const __half* Kp = g_Kh + head_off;
    const __half* Vp = g_Vh + head_off;
    const float SC = SCALE_C;

    const int nkt = q0 / 64 + 2;         // causal: KV tiles with k0 < q0+128
    const int tm = warp;                 // row band [warp*16, warp*16+16)

    ld_kv_h(Kp, Vp, KB, VB, 0, tid);
    cp_commit();

    // Row-index pattern (learn accumulator-fragment row mapping at runtime)
    if (tid < 256) Ss[(tid >> 4) * 68 + (tid & 15)] = (float)(tid >> 4);
    // Load Q tile (128 x 128 half): 2048 f4, 8 per thread
#pragma unroll
    for (int i = 0; i < 8; i++) {
        int fi = tid + BDIM * i;
        int r  = fi >> 4;
        int c8 = (fi & 15) * 8;
        *(uint4*)((char*)Qs + (r * QST + c8) * 2) =
            *(const uint4*)(Qp + (size_t)(q0 + r) * DHc + c8);
    }
    __syncthreads();
    wmma::fragment<wmma::accumulator, 16, 16, 16, float> rowf;
    wmma::load_matrix_sync(rowf, Ss, 68, wmma::mem_row_major);

    wmma::fragment<wmma::accumulator, 16, 16, 16, float> of[8];
#pragma unroll
    for (int j = 0; j < 8; j++) wmma::fill_fragment(of[j], 0.0f);

    float mreg = -1e30f, lreg = 0.0f;    // replicated per thread-pair

    for (int kt = 0; kt < nkt; kt++) {
        const int k0 = kt * 64;
        const __half* Ks = (const __half*)(KB + (kt & 1) * KVB);
        const __half* Vs = (const __half*)(VB + (kt & 1) * KVB);

        cp_wait<0>();
        __syncthreads();
        if (kt + 1 < nkt) {
            ld_kv_h(Kp, Vp, KB + ((kt + 1) & 1) * KVB, VB + ((kt + 1) & 1) * KVB,
                    (kt + 1) * 64, tid);
        }
        cp_commit();

        // S = Q K^T (128x64): warp computes row band tm, 4 col tiles
#pragma unroll
        for (int j = 0; j < 4; j++) {
            wmma::fragment<wmma::accumulator, 16, 16, 16, float> sf;
            wmma::fill_fragment(sf, 0.0f);
#pragma unroll
            for (int kk = 0; kk < 128; kk += 16) {
                wmma::fragment<wmma::matrix_a, 16, 16, 16, __half, wmma::row_major> af;
                wmma::fragment<wmma::matrix_b, 16, 16, 16, __half, wmma::col_major> bf;
                wmma::load_matrix_sync(af, Qs + (tm * 16) * QST + kk, QST);
                wmma::load_matrix_sync(bf, Ks + (j * 16) * QST + kk, QST);
                wmma::mma_sync(sf, af, bf, sf);
            }
            wmma::store_matrix_sync(Ss + (tm * 16) * 68 + j * 16, sf, 68, wmma::mem_row_major);
        }
        __syncthreads();

        // Online softmax: 2 threads per row (128 rows); P stored as fp16
        {
            int row = tid >> 1;
            int sub = tid & 1;
            int q = q0 + row;
            int vis = q - k0;            // columns c <= vis visible (may be < 0)
            float* srow = Ss + row * 68;
            __half* prow = Ps + row * PST;
            float mx = -1e30f;
#pragma unroll
            for (int c = sub * 32; c < sub * 32 + 32; c++)
                if (c <= vis) mx = fmaxf(mx, srow[c]);
            mx = fmaxf(mx, __shfl_xor_sync(0xffffffffu, mx, 1));
            float mn = fmaxf(mreg, mx * SC);
            float alpha = __expf(mreg - mn);
            float sum = 0.0f;
#pragma unroll
            for (int c = sub * 32; c < sub * 32 + 32; c++) {
                float p = (c <= vis) ? __expf(srow[c] * SC - mn) : 0.0f;
                __half ph = __float2half(p);
                prow[c] = ph;
                sum += __half2float(ph);
            }
            sum += __shfl_xor_sync(0xffffffffu, sum, 1);
            lreg = lreg * alpha + sum;
            mreg = mn;
            if (sub == 0) Ar[row] = alpha;
        }
        __syncthreads();

        // Rescale persistent accumulators, then of += P * V (row band tm)
        {
            float av[8];
#pragma unroll
            for (int e = 0; e < 8; e++)
                av[e] = Ar[tm * 16 + (int)rowf.x[e]];
#pragma unroll
            for (int j = 0; j < 8; j++)
#pragma unroll
                for (int e = 0; e < 8; e++)
                    of[j].x[e] *= av[e];
        }
#pragma unroll
        for (int j = 0; j < 8; j++) {
#pragma unroll
            for (int kk = 0; kk < 64; kk += 16) {
                wmma::fragment<wmma::matrix_a, 16, 16, 16, __half, wmma::row_major> af;
                wmma::fragment<wmma::matrix_b, 16, 16, 16, __half, wmma::row_major> bf;
                wmma::load_matrix_sync(af, Ps + (tm * 16) * PST + kk, PST);
                wmma::load_matrix_sync(bf, Vs + kk * QST + j * 16, QST);
                wmma::mma_sync(of[j], af, bf, of[j]);
            }
        }
    }

    // Epilogue: accumulators + l -> smem (Ac reuses Qs/KB region), normalize
#pragma unroll
    for (int j = 0; j < 8; j++)
        wmma::store_matrix_sync(Ac + (tm * 16) * 132 + j * 16, of[j], 132, wmma::mem_row_major);
    if ((tid & 1) == 0) Lr[tid >> 1] = lreg;
    __syncthreads();

    for (int idx = tid; idx < 128 * 128; idx += BDIM) {
        int r = idx >> 7, d = idx & 127;
        size_t m = (size_t)bb * Lc + q0 + r;
        g_Ah[m * Dc + h * DHc + d] = __float2half(Ac[r * 132 + d] / Lr[r]);
    }
}

// ---------------------------------------------------------------------------
// Output projection: out = A * Wo^T, fragments stored directly. grid = (16, 32)
// ---------------------------------------------------------------------------
__global__ void __launch_bounds__(BDIM, 2)
oproj_kernel(float* __restrict__ out) {
    extern __shared__ __align__(16) char smc[];
    gemm_core_h<true>(g_Ah, g_Woh, smc, out);
}

// ---------------------------------------------------------------------------
extern "C" void kernel_launch(void* const* d_in, const int* in_sizes, int n_in,
                              void* d_out, int out_size) {
    const float* x    = (const float*)d_in[0];
    // d_in[1] = mask (unused: causal mask applied analytically)
    const float* cosT = (const float*)d_in[2];
    const float* sinT = (const float*)d_in[3];
    const float* wq   = (const float*)d_in[4];
    const float* wk   = (const float*)d_in[5];
    const float* wv   = (const float*)d_in[6];
    const float* wo   = (const float*)d_in[7];
    float* out = (float*)d_out;

    const int smemG = 2 * NSTG * HBUFB;   // 110592 (pipeline dominates cs 67584)
    const int smemA = 158720;

    cudaFuncSetAttribute(proj_kernel,  cudaFuncAttributeMaxDynamicSharedMemorySize, smemG);
    cudaFuncSetAttribute(oproj_kernel, cudaFuncAttributeMaxDynamicSharedMemorySize, smemG);
    cudaFuncSetAttribute(attn_kernel,  cudaFuncAttributeMaxDynamicSharedMemorySize, smemA);

    constexpr size_t NTOT = (size_t)Bc * Lc * Dc + 4 * (size_t)Dc * Dc;  // 25165824
    cvt_kernel<<<(unsigned)(NTOT / 8 / 256), 256>>>(x, wq, wk, wv, wo);
    proj_kernel<<<dim3(Dc / 128, (Bc * Lc) / 128, 3), BDIM, smemG>>>(cosT, sinT);
    attn_kernel<<<dim3(Lc / 128, Hc, Bc), BDIM, smemA>>>();
    oproj_kernel<<<dim3(Dc / 128, (Bc * Lc) / 128, 1), BDIM, smemG>>>(out);
}